// round 14
// baseline (speedup 1.0000x reference)
#include <cuda_runtime.h>
#include <stdint.h>

#define BS 32
#define N 512
#define IN_X 16
#define IN_E 5
#define IN_C 3
#define IN_BD 3
#define OUT_X 16
#define OUT_E 5
#define OUT_C 3
#define OUT_BD 3

#define XCAT_OFF   0
#define XCAT_SZ    (BS * N * (IN_X + OUT_X))          // 524288
#define CCAT_OFF   (XCAT_OFF + XCAT_SZ)
#define CCAT_SZ    (BS * N * (IN_C + OUT_C))          // 98304
#define E1_OFF     (CCAT_OFF + CCAT_SZ)               // 622592
#define E1_SZ      (BS * N * N * OUT_E)               // 41943040
#define E2_OFF     (E1_OFF + E1_SZ)
#define BD1_OFF    (E2_OFF + E1_SZ)

// ---------------------------------------------------------------------------
// FINAL. One block per (sample i, reactant row j1), 256 threads, 16384 blocks.
// Measured-best configuration, reproduced three times at 82.0 us / 5.58 TB/s:
//   - register-resident alignment prep (amn/ma in regs, only s_table in smem)
//   - lazy s_sp build (skipped entirely for unmapped rows, ~50% of blocks)
//   - dual-LDS inner loops (4 consecutive channel elems span exactly 2 j2)
//   - float4 __stcs (evict-first) stores; E1/E2 stores interleaved between
//     gather loads (interleaving fills gather-latency bubbles — separating
//     the streams measured -11%)
//   - 32 regs -> 8 CTA/SM, ~85% occupancy
// Kernel runs at the HBM write-path ceiling for its ~98%-write stream; all
// 439 MB of DRAM traffic is mandatory output.
// ---------------------------------------------------------------------------
__global__ __launch_bounds__(256) void fused_kernel(
    const float* __restrict__ X,
    const float* __restrict__ E,
    const float* __restrict__ AC,
    const float* __restrict__ BD,
    const int*   __restrict__ AMN,
    const int*   __restrict__ MA,
    float* __restrict__ out)
{
    __shared__ int s_table[N + 1];   // table[m] = product pos + 1 (0 = absent)
    __shared__ int s_sp[N + 1];      // prodpos per reactant slot (lazy)
    __shared__ int s_max;
    __shared__ int s_p1;

    const int b   = blockIdx.x;
    const int i   = b >> 9;
    const int j1  = b & (N - 1);
    const int tid = threadIdx.x;

    // ---- prep: load amn/ma into regs, zero table ----
    const int j0 = tid, jh = tid + 256;
    const int a0 = AMN[i * N + j0];
    const int m0 = MA[i * N + j0];
    const int a1 = AMN[i * N + jh];
    const int m1 = MA[i * N + jh];
    s_table[j0] = 0;
    s_table[jh] = 0;
    if (tid == 0) { s_max = -2147483647; s_table[N] = 0; s_sp[N] = -1; }

    int mymax = max(m0, m1);
    #pragma unroll
    for (int off = 16; off; off >>= 1)
        mymax = max(mymax, __shfl_xor_sync(0xffffffffu, mymax, off));
    __syncthreads();
    if ((tid & 31) == 0) atomicMax(&s_max, mymax);
    __syncthreads();
    const int pa = s_max;

    // product-side scatter: table[amn] = pos + 1
    if (m0 == pa && a0 > 0 && a0 <= N) s_table[a0] = j0 + 1;
    if (m1 == pa && a1 > 0 && a1 <= N) s_table[a1] = jh + 1;
    __syncthreads();

    // this row's aligned product position (owning thread broadcasts)
    if ((j1 & 255) == tid) {
        const bool hi = (j1 >= 256);
        const int  a  = hi ? a1 : a0;
        const int  m  = hi ? m1 : m0;
        int pp = -1;
        if (m < pa && a > 0 && a <= N) {
            const int t = s_table[a];
            if (t > 0) pp = t - 1;
        }
        s_p1 = pp;
    }
    __syncthreads();
    const int p1 = s_p1;

    const int row = b;
    // ---- node features (38 floats for this row) ----
    if (tid < 32) {
        float v;
        if (tid < IN_X) v = X[row * IN_X + tid];
        else            v = (p1 >= 0) ? __ldg(&X[(i * N + p1) * IN_X + (tid - IN_X)]) : 0.0f;
        out[XCAT_OFF + row * (IN_X + OUT_X) + tid] = v;
    } else if (tid < 38) {
        const int c = tid - 32;
        float v;
        if (c < IN_C) v = AC[row * IN_C + c];
        else          v = (p1 >= 0) ? __ldg(&AC[(i * N + p1) * IN_C + (c - IN_C)]) : 0.0f;
        out[CCAT_OFF + row * (IN_C + OUT_C) + c] = v;
    }

    float4* __restrict__ e1v = reinterpret_cast<float4*>(out + E1_OFF  + (size_t)row * (N * OUT_E));
    float4* __restrict__ e2v = reinterpret_cast<float4*>(out + E2_OFF  + (size_t)row * (N * OUT_E));
    float4* __restrict__ bdv = reinterpret_cast<float4*>(out + BD1_OFF + (size_t)row * (N * OUT_BD));

    if (p1 < 0) {
        // ---- unmapped row: pure vectorized fills ----
        const float4 z4 = make_float4(0.f, 0.f, 0.f, 0.f);
        float4 pat[5];
        pat[0] = make_float4(1.f, 0.f, 0.f, 0.f);
        pat[1] = make_float4(0.f, 1.f, 0.f, 0.f);
        pat[2] = make_float4(0.f, 0.f, 1.f, 0.f);
        pat[3] = make_float4(0.f, 0.f, 0.f, 1.f);
        pat[4] = z4;
        #pragma unroll
        for (int k = tid; k < (N * OUT_E) / 4; k += 256) {   // 640 vecs
            __stcs(&e1v[k], z4);
            __stcs(&e2v[k], pat[k % 5]);
        }
        #pragma unroll
        for (int k = tid; k < (N * OUT_BD) / 4; k += 256) {  // 384 vecs
            __stcs(&bdv[k], z4);
        }
        return;
    }

    // ---- mapped row: build full prodpos table (lazy), then gather ----
    {
        int pp0 = -1, pp1 = -1;
        if (m0 < pa && a0 > 0 && a0 <= N) { const int t = s_table[a0]; if (t > 0) pp0 = t - 1; }
        if (m1 < pa && a1 > 0 && a1 <= N) { const int t = s_table[a1]; if (t > 0) pp1 = t - 1; }
        s_sp[j0] = pp0;
        s_sp[jh] = pp1;
    }
    __syncthreads();

    const float* __restrict__ Erow  = E  + (size_t)(i * N + p1) * N * IN_E;
    const float* __restrict__ BDrow = BD + (size_t)(i * N + p1) * N * IN_BD;

    // E1 / E2: 640 float4; 4 consecutive elems span exactly 2 j2 values
    #pragma unroll
    for (int it = 0; it < 3; it++) {                  // covers k < 640 with stride 256
        const int k = tid + it * 256;
        if (k >= (N * OUT_E) / 4) break;
        const int e0 = 4 * k;
        const int q  = e0 / 5;
        const int r0 = e0 - 5 * q;
        const int pA = s_sp[q];
        const int pB = s_sp[q + 1];
        float v1[4], v2[4];
        #pragma unroll
        for (int c4 = 0; c4 < 4; c4++) {
            const int idx = r0 + c4;
            const bool hi = (idx >= 5);
            const int c   = hi ? idx - 5 : idx;
            const int p2  = hi ? pB : pA;
            if (p2 >= 0) {
                v1[c4] = __ldg(&Erow[p2 * IN_E + c]);
                v2[c4] = 0.0f;
            } else {
                v1[c4] = 0.0f;
                v2[c4] = (c == 0) ? 1.0f : 0.0f;
            }
        }
        __stcs(&e1v[k], make_float4(v1[0], v1[1], v1[2], v1[3]));
        __stcs(&e2v[k], make_float4(v2[0], v2[1], v2[2], v2[3]));
    }

    // BD1: 384 float4
    #pragma unroll
    for (int it = 0; it < 2; it++) {
        const int k = tid + it * 256;
        if (k >= (N * OUT_BD) / 4) break;
        const int e0 = 4 * k;
        const int q  = e0 / 3;
        const int r0 = e0 - 3 * q;
        const int pA = s_sp[q];
        const int pB = s_sp[q + 1];
        float v[4];
        #pragma unroll
        for (int c4 = 0; c4 < 4; c4++) {
            const int idx = r0 + c4;
            const bool hi = (idx >= 3);
            const int c   = hi ? idx - 3 : idx;
            const int p2  = hi ? pB : pA;
            v[c4] = (p2 >= 0) ? __ldg(&BDrow[p2 * IN_BD + c]) : 0.0f;
        }
        __stcs(&bdv[k], make_float4(v[0], v[1], v[2], v[3]));
    }
}

// ---------------------------------------------------------------------------
extern "C" void kernel_launch(void* const* d_in, const int* in_sizes, int n_in,
                              void* d_out, int out_size) {
    const float* X   = (const float*)d_in[0];
    const float* E   = (const float*)d_in[1];
    const float* AC  = (const float*)d_in[2];
    const float* BD  = (const float*)d_in[3];
    const int*   AMN = (const int*)d_in[4];
    const int*   MA  = (const int*)d_in[5];
    float* out = (float*)d_out;

    fused_kernel<<<BS * N, 256>>>(X, E, AC, BD, AMN, MA, out);
}

// round 15
// speedup vs baseline: 1.3235x; 1.3235x over previous
#include <cuda_runtime.h>
#include <stdint.h>

#define BS 32
#define N 512
#define IN_X 16
#define IN_E 5
#define IN_C 3
#define IN_BD 3
#define OUT_X 16
#define OUT_E 5
#define OUT_C 3
#define OUT_BD 3

#define XCAT_OFF   0
#define XCAT_SZ    (BS * N * (IN_X + OUT_X))          // 524288
#define CCAT_OFF   (XCAT_OFF + XCAT_SZ)
#define CCAT_SZ    (BS * N * (IN_C + OUT_C))          // 98304
#define E1_OFF     (CCAT_OFF + CCAT_SZ)               // 622592
#define E1_SZ      (BS * N * N * OUT_E)               // 41943040
#define E2_OFF     (E1_OFF + E1_SZ)
#define BD1_OFF    (E2_OFF + E1_SZ)

// ---------------------------------------------------------------------------
// FINAL. One block per (sample i, reactant row j1), 256 threads, 16384 blocks.
// Measured-best configuration, reproduced three times at 82.0 us / 5.58 TB/s
// (R14's 109 us on identical source was an environmental outlier: same SASS,
// same occupancy, machine delivered 4.1 TB/s instead of 5.6 TB/s).
//   - register-resident alignment prep (amn/ma in regs, only s_table in smem)
//   - lazy s_sp build (skipped entirely for unmapped rows, ~50% of blocks)
//   - dual-LDS inner loops (4 consecutive channel elems span exactly 2 j2)
//   - float4 __stcs (evict-first) stores; E1/E2 stores interleaved between
//     gather loads (separating the streams measured -11%)
//   - 32 regs -> 8 CTA/SM, ~85% occupancy
// Kernel runs at the HBM write-path ceiling for its ~98%-write stream; all
// 439 MB of DRAM traffic is mandatory output.
// ---------------------------------------------------------------------------
__global__ __launch_bounds__(256) void fused_kernel(
    const float* __restrict__ X,
    const float* __restrict__ E,
    const float* __restrict__ AC,
    const float* __restrict__ BD,
    const int*   __restrict__ AMN,
    const int*   __restrict__ MA,
    float* __restrict__ out)
{
    __shared__ int s_table[N + 1];   // table[m] = product pos + 1 (0 = absent)
    __shared__ int s_sp[N + 1];      // prodpos per reactant slot (lazy)
    __shared__ int s_max;
    __shared__ int s_p1;

    const int b   = blockIdx.x;
    const int i   = b >> 9;
    const int j1  = b & (N - 1);
    const int tid = threadIdx.x;

    // ---- prep: load amn/ma into regs, zero table ----
    const int j0 = tid, jh = tid + 256;
    const int a0 = AMN[i * N + j0];
    const int m0 = MA[i * N + j0];
    const int a1 = AMN[i * N + jh];
    const int m1 = MA[i * N + jh];
    s_table[j0] = 0;
    s_table[jh] = 0;
    if (tid == 0) { s_max = -2147483647; s_table[N] = 0; s_sp[N] = -1; }

    int mymax = max(m0, m1);
    #pragma unroll
    for (int off = 16; off; off >>= 1)
        mymax = max(mymax, __shfl_xor_sync(0xffffffffu, mymax, off));
    __syncthreads();
    if ((tid & 31) == 0) atomicMax(&s_max, mymax);
    __syncthreads();
    const int pa = s_max;

    // product-side scatter: table[amn] = pos + 1
    if (m0 == pa && a0 > 0 && a0 <= N) s_table[a0] = j0 + 1;
    if (m1 == pa && a1 > 0 && a1 <= N) s_table[a1] = jh + 1;
    __syncthreads();

    // this row's aligned product position (owning thread broadcasts)
    if ((j1 & 255) == tid) {
        const bool hi = (j1 >= 256);
        const int  a  = hi ? a1 : a0;
        const int  m  = hi ? m1 : m0;
        int pp = -1;
        if (m < pa && a > 0 && a <= N) {
            const int t = s_table[a];
            if (t > 0) pp = t - 1;
        }
        s_p1 = pp;
    }
    __syncthreads();
    const int p1 = s_p1;

    const int row = b;
    // ---- node features (38 floats for this row) ----
    if (tid < 32) {
        float v;
        if (tid < IN_X) v = X[row * IN_X + tid];
        else            v = (p1 >= 0) ? __ldg(&X[(i * N + p1) * IN_X + (tid - IN_X)]) : 0.0f;
        out[XCAT_OFF + row * (IN_X + OUT_X) + tid] = v;
    } else if (tid < 38) {
        const int c = tid - 32;
        float v;
        if (c < IN_C) v = AC[row * IN_C + c];
        else          v = (p1 >= 0) ? __ldg(&AC[(i * N + p1) * IN_C + (c - IN_C)]) : 0.0f;
        out[CCAT_OFF + row * (IN_C + OUT_C) + c] = v;
    }

    float4* __restrict__ e1v = reinterpret_cast<float4*>(out + E1_OFF  + (size_t)row * (N * OUT_E));
    float4* __restrict__ e2v = reinterpret_cast<float4*>(out + E2_OFF  + (size_t)row * (N * OUT_E));
    float4* __restrict__ bdv = reinterpret_cast<float4*>(out + BD1_OFF + (size_t)row * (N * OUT_BD));

    if (p1 < 0) {
        // ---- unmapped row: pure vectorized fills ----
        const float4 z4 = make_float4(0.f, 0.f, 0.f, 0.f);
        float4 pat[5];
        pat[0] = make_float4(1.f, 0.f, 0.f, 0.f);
        pat[1] = make_float4(0.f, 1.f, 0.f, 0.f);
        pat[2] = make_float4(0.f, 0.f, 1.f, 0.f);
        pat[3] = make_float4(0.f, 0.f, 0.f, 1.f);
        pat[4] = z4;
        #pragma unroll
        for (int k = tid; k < (N * OUT_E) / 4; k += 256) {   // 640 vecs
            __stcs(&e1v[k], z4);
            __stcs(&e2v[k], pat[k % 5]);
        }
        #pragma unroll
        for (int k = tid; k < (N * OUT_BD) / 4; k += 256) {  // 384 vecs
            __stcs(&bdv[k], z4);
        }
        return;
    }

    // ---- mapped row: build full prodpos table (lazy), then gather ----
    {
        int pp0 = -1, pp1 = -1;
        if (m0 < pa && a0 > 0 && a0 <= N) { const int t = s_table[a0]; if (t > 0) pp0 = t - 1; }
        if (m1 < pa && a1 > 0 && a1 <= N) { const int t = s_table[a1]; if (t > 0) pp1 = t - 1; }
        s_sp[j0] = pp0;
        s_sp[jh] = pp1;
    }
    __syncthreads();

    const float* __restrict__ Erow  = E  + (size_t)(i * N + p1) * N * IN_E;
    const float* __restrict__ BDrow = BD + (size_t)(i * N + p1) * N * IN_BD;

    // E1 / E2: 640 float4; 4 consecutive elems span exactly 2 j2 values
    #pragma unroll
    for (int it = 0; it < 3; it++) {                  // covers k < 640 with stride 256
        const int k = tid + it * 256;
        if (k >= (N * OUT_E) / 4) break;
        const int e0 = 4 * k;
        const int q  = e0 / 5;
        const int r0 = e0 - 5 * q;
        const int pA = s_sp[q];
        const int pB = s_sp[q + 1];
        float v1[4], v2[4];
        #pragma unroll
        for (int c4 = 0; c4 < 4; c4++) {
            const int idx = r0 + c4;
            const bool hi = (idx >= 5);
            const int c   = hi ? idx - 5 : idx;
            const int p2  = hi ? pB : pA;
            if (p2 >= 0) {
                v1[c4] = __ldg(&Erow[p2 * IN_E + c]);
                v2[c4] = 0.0f;
            } else {
                v1[c4] = 0.0f;
                v2[c4] = (c == 0) ? 1.0f : 0.0f;
            }
        }
        __stcs(&e1v[k], make_float4(v1[0], v1[1], v1[2], v1[3]));
        __stcs(&e2v[k], make_float4(v2[0], v2[1], v2[2], v2[3]));
    }

    // BD1: 384 float4
    #pragma unroll
    for (int it = 0; it < 2; it++) {
        const int k = tid + it * 256;
        if (k >= (N * OUT_BD) / 4) break;
        const int e0 = 4 * k;
        const int q  = e0 / 3;
        const int r0 = e0 - 3 * q;
        const int pA = s_sp[q];
        const int pB = s_sp[q + 1];
        float v[4];
        #pragma unroll
        for (int c4 = 0; c4 < 4; c4++) {
            const int idx = r0 + c4;
            const bool hi = (idx >= 3);
            const int c   = hi ? idx - 3 : idx;
            const int p2  = hi ? pB : pA;
            v[c4] = (p2 >= 0) ? __ldg(&BDrow[p2 * IN_BD + c]) : 0.0f;
        }
        __stcs(&bdv[k], make_float4(v[0], v[1], v[2], v[3]));
    }
}

// ---------------------------------------------------------------------------
extern "C" void kernel_launch(void* const* d_in, const int* in_sizes, int n_in,
                              void* d_out, int out_size) {
    const float* X   = (const float*)d_in[0];
    const float* E   = (const float*)d_in[1];
    const float* AC  = (const float*)d_in[2];
    const float* BD  = (const float*)d_in[3];
    const int*   AMN = (const int*)d_in[4];
    const int*   MA  = (const int*)d_in[5];
    float* out = (float*)d_out;

    fused_kernel<<<BS * N, 256>>>(X, E, AC, BD, AMN, MA, out);
}

// round 16
// speedup vs baseline: 1.3307x; 1.0055x over previous
#include <cuda_runtime.h>
#include <stdint.h>

#define BS 32
#define N 512
#define IN_X 16
#define IN_E 5
#define IN_C 3
#define IN_BD 3
#define OUT_X 16
#define OUT_E 5
#define OUT_C 3
#define OUT_BD 3

#define XCAT_OFF   0
#define XCAT_SZ    (BS * N * (IN_X + OUT_X))          // 524288
#define CCAT_OFF   (XCAT_OFF + XCAT_SZ)
#define CCAT_SZ    (BS * N * (IN_C + OUT_C))          // 98304
#define E1_OFF     (CCAT_OFF + CCAT_SZ)               // 622592
#define E1_SZ      (BS * N * N * OUT_E)               // 41943040
#define E2_OFF     (E1_OFF + E1_SZ)
#define BD1_OFF    (E2_OFF + E1_SZ)

// ---------------------------------------------------------------------------
// One block per (sample i, reactant row j1), 256 threads, 16384 blocks.
// Validated-optimum structure (4x reproduced at 82.0-82.4 us / 5.58 TB/s)
// with one prologue barrier removed: every thread loads this row's amn/ma
// directly (broadcast L1-hit load) and computes p1 locally, eliminating the
// s_p1 shared broadcast + its __syncthreads.
// ---------------------------------------------------------------------------
__global__ __launch_bounds__(256) void fused_kernel(
    const float* __restrict__ X,
    const float* __restrict__ E,
    const float* __restrict__ AC,
    const float* __restrict__ BD,
    const int*   __restrict__ AMN,
    const int*   __restrict__ MA,
    float* __restrict__ out)
{
    __shared__ int s_table[N + 1];   // table[m] = product pos + 1 (0 = absent)
    __shared__ int s_sp[N + 1];      // prodpos per reactant slot (lazy)
    __shared__ int s_max;

    const int b   = blockIdx.x;
    const int i   = b >> 9;
    const int j1  = b & (N - 1);
    const int tid = threadIdx.x;

    // ---- prep: load amn/ma into regs, zero table ----
    const int j0 = tid, jh = tid + 256;
    const int a0 = AMN[i * N + j0];
    const int m0 = MA[i * N + j0];
    const int a1 = AMN[i * N + jh];
    const int m1 = MA[i * N + jh];
    const int aj = AMN[i * N + j1];   // broadcast load (same line set, L1-hit)
    const int mj = MA[i * N + j1];
    s_table[j0] = 0;
    s_table[jh] = 0;
    if (tid == 0) { s_max = -2147483647; s_table[N] = 0; s_sp[N] = -1; }

    int mymax = max(m0, m1);
    #pragma unroll
    for (int off = 16; off; off >>= 1)
        mymax = max(mymax, __shfl_xor_sync(0xffffffffu, mymax, off));
    __syncthreads();
    if ((tid & 31) == 0) atomicMax(&s_max, mymax);
    __syncthreads();
    const int pa = s_max;

    // product-side scatter: table[amn] = pos + 1
    if (m0 == pa && a0 > 0 && a0 <= N) s_table[a0] = j0 + 1;
    if (m1 == pa && a1 > 0 && a1 <= N) s_table[a1] = jh + 1;
    __syncthreads();

    // this row's aligned product position — computed by every thread locally
    int p1 = -1;
    if (mj < pa && aj > 0 && aj <= N) {
        const int t = s_table[aj];
        if (t > 0) p1 = t - 1;
    }

    const int row = b;
    // ---- node features (38 floats for this row) ----
    if (tid < 32) {
        float v;
        if (tid < IN_X) v = X[row * IN_X + tid];
        else            v = (p1 >= 0) ? __ldg(&X[(i * N + p1) * IN_X + (tid - IN_X)]) : 0.0f;
        out[XCAT_OFF + row * (IN_X + OUT_X) + tid] = v;
    } else if (tid < 38) {
        const int c = tid - 32;
        float v;
        if (c < IN_C) v = AC[row * IN_C + c];
        else          v = (p1 >= 0) ? __ldg(&AC[(i * N + p1) * IN_C + (c - IN_C)]) : 0.0f;
        out[CCAT_OFF + row * (IN_C + OUT_C) + c] = v;
    }

    float4* __restrict__ e1v = reinterpret_cast<float4*>(out + E1_OFF  + (size_t)row * (N * OUT_E));
    float4* __restrict__ e2v = reinterpret_cast<float4*>(out + E2_OFF  + (size_t)row * (N * OUT_E));
    float4* __restrict__ bdv = reinterpret_cast<float4*>(out + BD1_OFF + (size_t)row * (N * OUT_BD));

    if (p1 < 0) {
        // ---- unmapped row: pure vectorized fills ----
        const float4 z4 = make_float4(0.f, 0.f, 0.f, 0.f);
        float4 pat[5];
        pat[0] = make_float4(1.f, 0.f, 0.f, 0.f);
        pat[1] = make_float4(0.f, 1.f, 0.f, 0.f);
        pat[2] = make_float4(0.f, 0.f, 1.f, 0.f);
        pat[3] = make_float4(0.f, 0.f, 0.f, 1.f);
        pat[4] = z4;
        #pragma unroll
        for (int k = tid; k < (N * OUT_E) / 4; k += 256) {   // 640 vecs
            __stcs(&e1v[k], z4);
            __stcs(&e2v[k], pat[k % 5]);
        }
        #pragma unroll
        for (int k = tid; k < (N * OUT_BD) / 4; k += 256) {  // 384 vecs
            __stcs(&bdv[k], z4);
        }
        return;
    }

    // ---- mapped row: build full prodpos table (lazy), then gather ----
    {
        int pp0 = -1, pp1 = -1;
        if (m0 < pa && a0 > 0 && a0 <= N) { const int t = s_table[a0]; if (t > 0) pp0 = t - 1; }
        if (m1 < pa && a1 > 0 && a1 <= N) { const int t = s_table[a1]; if (t > 0) pp1 = t - 1; }
        s_sp[j0] = pp0;
        s_sp[jh] = pp1;
    }
    __syncthreads();

    const float* __restrict__ Erow  = E  + (size_t)(i * N + p1) * N * IN_E;
    const float* __restrict__ BDrow = BD + (size_t)(i * N + p1) * N * IN_BD;

    // E1 / E2: 640 float4; 4 consecutive elems span exactly 2 j2 values
    #pragma unroll
    for (int it = 0; it < 3; it++) {                  // covers k < 640 with stride 256
        const int k = tid + it * 256;
        if (k >= (N * OUT_E) / 4) break;
        const int e0 = 4 * k;
        const int q  = e0 / 5;
        const int r0 = e0 - 5 * q;
        const int pA = s_sp[q];
        const int pB = s_sp[q + 1];
        float v1[4], v2[4];
        #pragma unroll
        for (int c4 = 0; c4 < 4; c4++) {
            const int idx = r0 + c4;
            const bool hi = (idx >= 5);
            const int c   = hi ? idx - 5 : idx;
            const int p2  = hi ? pB : pA;
            if (p2 >= 0) {
                v1[c4] = __ldg(&Erow[p2 * IN_E + c]);
                v2[c4] = 0.0f;
            } else {
                v1[c4] = 0.0f;
                v2[c4] = (c == 0) ? 1.0f : 0.0f;
            }
        }
        __stcs(&e1v[k], make_float4(v1[0], v1[1], v1[2], v1[3]));
        __stcs(&e2v[k], make_float4(v2[0], v2[1], v2[2], v2[3]));
    }

    // BD1: 384 float4
    #pragma unroll
    for (int it = 0; it < 2; it++) {
        const int k = tid + it * 256;
        if (k >= (N * OUT_BD) / 4) break;
        const int e0 = 4 * k;
        const int q  = e0 / 3;
        const int r0 = e0 - 3 * q;
        const int pA = s_sp[q];
        const int pB = s_sp[q + 1];
        float v[4];
        #pragma unroll
        for (int c4 = 0; c4 < 4; c4++) {
            const int idx = r0 + c4;
            const bool hi = (idx >= 3);
            const int c   = hi ? idx - 3 : idx;
            const int p2  = hi ? pB : pA;
            v[c4] = (p2 >= 0) ? __ldg(&BDrow[p2 * IN_BD + c]) : 0.0f;
        }
        __stcs(&bdv[k], make_float4(v[0], v[1], v[2], v[3]));
    }
}

// ---------------------------------------------------------------------------
extern "C" void kernel_launch(void* const* d_in, const int* in_sizes, int n_in,
                              void* d_out, int out_size) {
    const float* X   = (const float*)d_in[0];
    const float* E   = (const float*)d_in[1];
    const float* AC  = (const float*)d_in[2];
    const float* BD  = (const float*)d_in[3];
    const int*   AMN = (const int*)d_in[4];
    const int*   MA  = (const int*)d_in[5];
    float* out = (float*)d_out;

    fused_kernel<<<BS * N, 256>>>(X, E, AC, BD, AMN, MA, out);
}